// round 7
// baseline (speedup 1.0000x reference)
#include <cuda_runtime.h>
#include <cuda_bf16.h>

// ---------------- problem constants ----------------
#define BB 16
#define LL 2048
#define TT (BB*LL)          // 32768 tokens
#define IND 57
#define DM 64
#define DI 128              // d_inner
#define HH 4                // heads
#define PP 32               // headdim
#define NN 32               // d_state
#define DXBC 192
#define DPROJ 324
#define QQ 32               // chunk length
#define NC (LL/QQ)          // 64 chunks per sequence

// ---------------- scratch (device globals; no runtime alloc) ----------------
__device__ float g_h[TT*DM];          // 8 MB
__device__ float g_z[TT*DI];          // silu(z), 16 MB
__device__ float g_xbc[TT*DXBC];      // pre-conv, 24 MB
__device__ float g_xbc2[TT*DXBC];     // post conv+silu, 24 MB
__device__ float g_dt[TT*HH];         // softplus(dt + bias)
__device__ float g_alpha[BB*HH*LL];   // within-chunk inclusive cumsum of dt*A
__device__ float g_y[TT*DI];          // scan output (intra + D*x, then += inter)
__device__ float g_S[BB*HH*NC*PP*NN]; // 16 MB chunk-local states
__device__ float g_H0[BB*HH*NC*PP*NN];// 16 MB state entering each chunk
__device__ float g_cdecay[BB*HH*NC];
__device__ float g_pool[BB*DI];

__device__ __forceinline__ float silu_f(float v) {
    return v / (1.f + __expf(-v));
}
__device__ __forceinline__ float softplus_f(float v) {
    return (v > 15.f) ? v : log1pf(__expf(v));
}

// ---------------- K0: zero the pooling accumulator ----------------
__global__ void k_zero_pool() {
    int i = blockIdx.x * 256 + threadIdx.x;
    if (i < BB*DI) g_pool[i] = 0.f;
}

// ---------------- K1: h = x @ W_lin + b_lin ----------------
__global__ void k_lin(const float* __restrict__ x,
                      const float* __restrict__ Wl,
                      const float* __restrict__ bl) {
    __shared__ float sx[64][IND+1];
    __shared__ float sw[IND][DM];
    int t0 = blockIdx.x * 64;
    for (int i = threadIdx.x; i < 64*IND; i += 256) {
        int r = i / IND, k = i % IND;
        sx[r][k] = x[(size_t)(t0+r)*IND + k];
    }
    for (int i = threadIdx.x; i < IND*DM; i += 256)
        sw[i/DM][i%DM] = Wl[i];
    __syncthreads();
    int col = threadIdx.x & 63;
    int r0  = threadIdx.x >> 6;
    float bv = bl[col];
    for (int rr = r0; rr < 64; rr += 4) {
        float acc = bv;
        #pragma unroll
        for (int k = 0; k < IND; k++) acc += sx[rr][k]*sw[k][col];
        g_h[(size_t)(t0+rr)*DM + col] = acc;
    }
}

// ---------------- K2: zxbcdt = h @ W_in, split + activations ----------------
// block: 64 tokens, 256 threads, 4x4 register tiles, float4 W loads
__global__ void k_inproj(const float* __restrict__ Win,
                         const float* __restrict__ dt_bias) {
    __shared__ float sh[64][DM];
    int t0 = blockIdx.x * 64;
    for (int i = threadIdx.x; i < 64*DM; i += 256)
        sh[i>>6][i&63] = g_h[(size_t)t0*DM + i];
    __syncthreads();

    for (int tile = threadIdx.x; tile < 16*81; tile += 256) {
        int tq = tile / 81;          // token quad
        int cq = tile % 81;          // col quad (324/4)
        int c0 = cq * 4;
        float acc[4][4] = {};
        #pragma unroll 8
        for (int k = 0; k < DM; k++) {
            float4 w = *reinterpret_cast<const float4*>(Win + (size_t)k*DPROJ + c0);
            #pragma unroll
            for (int i = 0; i < 4; i++) {
                float hv = sh[tq*4 + i][k];
                acc[i][0] += hv*w.x; acc[i][1] += hv*w.y;
                acc[i][2] += hv*w.z; acc[i][3] += hv*w.w;
            }
        }
        #pragma unroll
        for (int i = 0; i < 4; i++) {
            int tok = t0 + tq*4 + i;
            #pragma unroll
            for (int j = 0; j < 4; j++) {
                int cc = c0 + j;
                float v = acc[i][j];
                if (cc < DI) {
                    g_z[(size_t)tok*DI + cc] = silu_f(v);
                } else if (cc < DI + DXBC) {
                    g_xbc[(size_t)tok*DXBC + (cc - DI)] = v;
                } else {
                    int hd = cc - (DI + DXBC);
                    g_dt[(size_t)tok*HH + hd] = softplus_f(v + dt_bias[hd]);
                }
            }
        }
    }
}

// ---------------- K3: depthwise causal conv + silu ----------------
__global__ void k_conv(const float* __restrict__ cw,
                       const float* __restrict__ cb) {
    long long idx = (long long)blockIdx.x * 256 + threadIdx.x;
    if (idx >= (long long)TT*DXBC) return;
    int c = (int)(idx % DXBC);
    long long tok = idx / DXBC;
    int l = (int)(tok % LL);
    float acc = cb[c];
    #pragma unroll
    for (int k = 0; k < 4; k++) {
        int ls = l - 3 + k;
        if (ls >= 0)
            acc += cw[c*4 + k] * g_xbc[(tok - 3 + k)*DXBC + c];
    }
    g_xbc2[idx] = silu_f(acc);
}

// ---------------- K4: phase A — chunk-local scan as small matmuls ----------------
// block = (b, h, chunk), 256 threads
__global__ void k_phaseA(const float* __restrict__ A_log,
                         const float* __restrict__ Dp) {
    int bid = blockIdx.x;            // (b*H + h)*NC + c
    int c  = bid % NC;
    int bh = bid / NC;
    int hd = bh % HH;
    int b  = bh / HH;
    int tid = threadIdx.x;

    __shared__ float sx[QQ][33], sB[QQ][33], sC[QQ][33], sM[QQ][33], sxw[QQ][33];
    __shared__ float sdt[QQ], salpha[QQ], sE[QQ], sF[QQ], sw_[QQ];

    size_t lbase = (size_t)b*LL + (size_t)c*QQ;
    for (int i = tid; i < QQ*32; i += 256) {
        int t = i >> 5, j = i & 31;
        size_t base = (lbase + t) * DXBC;
        sx[t][j] = g_xbc2[base + hd*PP + j];
        sB[t][j] = g_xbc2[base + DI + j];
        sC[t][j] = g_xbc2[base + DI + NN + j];
    }
    if (tid < QQ) sdt[tid] = g_dt[(lbase + tid)*HH + hd];
    __syncthreads();

    if (tid == 0) {
        float A = -__expf(A_log[hd]);
        float acc = 0.f;
        for (int t = 0; t < QQ; t++) { acc += sdt[t]*A; salpha[t] = acc; }
        g_cdecay[bid] = __expf(acc);
    }
    __syncthreads();

    if (tid < QQ) {
        float am = salpha[QQ/2];
        float al = salpha[tid];
        sE[tid]  = __expf(al - am);
        sF[tid]  = __expf(am - al) * sdt[tid];
        sw_[tid] = __expf(salpha[QQ-1] - al) * sdt[tid];
        g_alpha[(size_t)bh*LL + c*QQ + tid] = al;
    }
    __syncthreads();

    // pass 1: M[t][s] = (C_t . B_s) * exp(a_t - a_s) * dt_s  (lower triangle)
    for (int e = tid; e < QQ*QQ; e += 256) {
        int t = e >> 5, s = e & 31;
        float m = 0.f;
        if (s <= t) {
            float d = 0.f;
            #pragma unroll 8
            for (int n = 0; n < 32; n++) d += sC[t][n]*sB[s][n];
            m = d * sE[t] * sF[s];
        }
        sM[t][s] = m;
    }
    // weighted x for the state contribution
    for (int i = tid; i < QQ*32; i += 256) {
        int s = i >> 5, p = i & 31;
        sxw[s][p] = sw_[s] * sx[s][p];
    }
    __syncthreads();

    // pass 2: Y_intra[t][p] = D*x + sum_{s<=t} M[t][s]*x_s[p]
    float Dh = Dp[hd];
    for (int e = tid; e < QQ*32; e += 256) {
        int t = e >> 5, p = e & 31;
        float y = Dh * sx[t][p];
        for (int s = 0; s <= t; s++) y += sM[t][s]*sx[s][p];
        g_y[(lbase + t)*DI + hd*PP + p] = y;
    }
    // S[p][n] = sum_s w_s x_s[p] B_s[n]
    for (int e = tid; e < PP*NN; e += 256) {
        int p = e >> 5, n = e & 31;
        float acc = 0.f;
        #pragma unroll 8
        for (int s = 0; s < QQ; s++) acc += sxw[s][p]*sB[s][n];
        g_S[(size_t)bid*1024 + e] = acc;
    }
}

// ---------------- K5: phase B — tiny sequential state recurrence ----------------
__global__ void k_phaseB() {
    int idx = blockIdx.x*256 + threadIdx.x;      // 0..65535
    int pn = idx & 1023;
    int bh = idx >> 10;
    float hcur = 0.f;
    #pragma unroll 4
    for (int c = 0; c < NC; c++) {
        size_t o = ((size_t)bh*NC + c)*1024 + pn;
        g_H0[o] = hcur;
        hcur = g_cdecay[bh*NC + c]*hcur + g_S[o];
    }
}

// ---------------- K6: phase C — inter-chunk contribution ----------------
__global__ void k_phaseC() {
    int bid = blockIdx.x;
    int c  = bid % NC;
    int bh = bid / NC;
    int hd = bh % HH;
    int b  = bh / HH;
    int tid = threadIdx.x;

    __shared__ float sH[PP][NN+1];
    __shared__ float sCt[QQ][33];
    __shared__ float sea[QQ];

    size_t lbase = (size_t)b*LL + (size_t)c*QQ;
    for (int i = tid; i < PP*NN; i += 256)
        sH[i>>5][i&31] = g_H0[(size_t)bid*1024 + i];
    for (int i = tid; i < QQ*32; i += 256) {
        int t = i >> 5, n = i & 31;
        sCt[t][n] = g_xbc2[(lbase + t)*DXBC + DI + NN + n];
    }
    if (tid < QQ) sea[tid] = __expf(g_alpha[(size_t)bh*LL + c*QQ + tid]);
    __syncthreads();

    for (int e = tid; e < QQ*32; e += 256) {
        int t = e >> 5, p = e & 31;
        float acc = 0.f;
        #pragma unroll 8
        for (int n = 0; n < 32; n++) acc += sH[p][n]*sCt[t][n];
        size_t o = (lbase + t)*DI + hd*PP + p;
        g_y[o] += acc * sea[t];
    }
}

// ---------------- K7: gate * silu(z), RMSNorm, pool over L ----------------
__global__ void k_gate_pool(const float* __restrict__ nw) {
    __shared__ float sv[64][DI+1];
    __shared__ float srms[64];
    int b   = blockIdx.x >> 5;
    int lt0 = (blockIdx.x & 31) * 64;
    int tid = threadIdx.x;

    for (int i = tid; i < 64*DI; i += 256) {
        int t = i >> 7, p = i & 127;
        size_t o = ((size_t)b*LL + lt0 + t)*DI + p;
        sv[t][p] = g_y[o]*g_z[o];
    }
    __syncthreads();
    if (tid < 64) {
        float ss = 0.f;
        #pragma unroll 8
        for (int p = 0; p < DI; p++) { float v = sv[tid][p]; ss += v*v; }
        srms[tid] = rsqrtf(ss*(1.f/DI) + 1e-5f);
    }
    __syncthreads();
    int p  = tid & 127;
    int g2 = tid >> 7;
    float acc = 0.f;
    #pragma unroll 8
    for (int t = g2*32; t < g2*32 + 32; t++) acc += sv[t][p]*srms[t];
    atomicAdd(&g_pool[b*DI + p], acc*nw[p]);
}

// ---------------- K8: (pool/L) @ W_out @ W_cls + b_cls ----------------
__global__ void k_final(const float* __restrict__ Wout,
                        const float* __restrict__ Wcls,
                        const float* __restrict__ bcls,
                        float* __restrict__ out) {
    __shared__ float sp[BB][DI];
    __shared__ float st[BB][DM+1];
    int tid = threadIdx.x;
    for (int i = tid; i < BB*DI; i += 256)
        sp[i>>7][i&127] = g_pool[i] * (1.f/LL);
    __syncthreads();
    for (int i = tid; i < BB*DM; i += 256) {
        int bb = i >> 6, j = i & 63;
        float acc = 0.f;
        #pragma unroll 8
        for (int p = 0; p < DI; p++) acc += sp[bb][p]*Wout[p*DM + j];
        st[bb][j] = acc;
    }
    __syncthreads();
    if (tid < BB*6) {
        int bb = tid / 6, o = tid % 6;
        float acc = bcls[o];
        #pragma unroll 8
        for (int j = 0; j < DM; j++) acc += st[bb][j]*Wcls[j*6 + o];
        out[bb*6 + o] = acc;
    }
}

// ---------------- launcher ----------------
extern "C" void kernel_launch(void* const* d_in, const int* in_sizes, int n_in,
                              void* d_out, int out_size) {
    const float* x       = (const float*)d_in[0];
    const float* W_lin   = (const float*)d_in[1];
    const float* b_lin   = (const float*)d_in[2];
    const float* W_in    = (const float*)d_in[3];
    const float* conv_w  = (const float*)d_in[4];
    const float* conv_b  = (const float*)d_in[5];
    const float* dt_bias = (const float*)d_in[6];
    const float* A_log   = (const float*)d_in[7];
    const float* Dp      = (const float*)d_in[8];
    const float* norm_w  = (const float*)d_in[9];
    const float* W_out   = (const float*)d_in[10];
    const float* W_cls   = (const float*)d_in[11];
    const float* b_cls   = (const float*)d_in[12];
    float* out = (float*)d_out;

    k_zero_pool<<<8, 256>>>();
    k_lin<<<TT/64, 256>>>(x, W_lin, b_lin);
    k_inproj<<<TT/64, 256>>>(W_in, dt_bias);
    {
        long long total = (long long)TT*DXBC;
        int grid = (int)((total + 255) / 256);
        k_conv<<<grid, 256>>>(conv_w, conv_b);
    }
    k_phaseA<<<BB*HH*NC, 256>>>(A_log, Dp);
    k_phaseB<<<(BB*HH*PP*NN)/256, 256>>>();
    k_phaseC<<<BB*HH*NC, 256>>>();
    k_gate_pool<<<BB*(LL/64), 256>>>(norm_w);
    k_final<<<1, 256>>>(W_out, W_cls, b_cls, out);
}

// round 8
// speedup vs baseline: 1.3280x; 1.3280x over previous
#include <cuda_runtime.h>
#include <cuda_bf16.h>

// ---------------- problem constants ----------------
#define BB 16
#define LL 2048
#define TT (BB*LL)          // 32768 tokens
#define IND 57
#define DM 64
#define DI 128              // d_inner
#define HH 4                // heads
#define PP 32               // headdim
#define NN 32               // d_state
#define DXBC 192
#define DPROJ 324
#define QQ 32               // chunk length
#define NC (LL/QQ)          // 64 chunks per sequence
#define PT 32               // tokens per proj block

// ---------------- scratch (device globals; no runtime alloc) ----------------
__device__ float g_Wc[IND*DPROJ];     // fused W_lin@W_in
__device__ float g_bc[DPROJ];         // fused bias
__device__ float g_z[TT*DI];          // silu(z)
__device__ float g_xbc2[TT*DXBC];     // post conv+silu
__device__ float g_dt[TT*HH];         // softplus(dt + bias)
__device__ float g_alpha[BB*HH*LL];   // within-chunk inclusive cumsum of dt*A
__device__ float g_y[TT*DI];          // scan output
__device__ float g_S[BB*HH*NC*PP*NN]; // chunk-local states
__device__ float g_H0[BB*HH*NC*PP*NN];// state entering each chunk
__device__ float g_cdecay[BB*HH*NC];
__device__ float g_pool[BB*DI];

__device__ __forceinline__ float silu_f(float v) {
    return v / (1.f + __expf(-v));
}
__device__ __forceinline__ float softplus_f(float v) {
    return (v > 15.f) ? v : log1pf(__expf(v));
}

// ---------------- K_pre: fused weight/bias + zero pool ----------------
// blocks 0..72: Wc/bc elements; block 73: zero g_pool
__global__ void k_pre(const float* __restrict__ Wl,
                      const float* __restrict__ bl,
                      const float* __restrict__ Win) {
    if (blockIdx.x == 73) {
        for (int i = threadIdx.x; i < BB*DI; i += 256) g_pool[i] = 0.f;
        return;
    }
    int idx = blockIdx.x * 256 + threadIdx.x;
    if (idx < IND*DPROJ) {
        int k = idx / DPROJ, c = idx % DPROJ;
        float acc = 0.f;
        #pragma unroll 8
        for (int m = 0; m < DM; m++) acc += Wl[k*DM + m] * Win[m*DPROJ + c];
        g_Wc[idx] = acc;
    } else if (idx < IND*DPROJ + DPROJ) {
        int c = idx - IND*DPROJ;
        float acc = 0.f;
        #pragma unroll 8
        for (int m = 0; m < DM; m++) acc += bl[m] * Win[m*DPROJ + c];
        g_bc[c] = acc;
    }
}

// ---------------- K_proj: x -> (z, xBC[conv+silu], dt) fused ----------------
// block = 32 tokens + 3-token halo recompute, 256 threads
__global__ void k_proj(const float* __restrict__ x,
                       const float* __restrict__ cw,
                       const float* __restrict__ cb,
                       const float* __restrict__ dt_bias) {
    __shared__ float sx[PT+3][IND];        // rows 0..2 halo, 3..34 main
    __shared__ float sxbc[PT+3][196];      // pre-conv xBC
    __shared__ float scw[DXBC*4];
    __shared__ float scb[DXBC];
    int tid = threadIdx.x;
    int t0  = blockIdx.x * PT;
    int l0  = t0 & (LL-1);                 // sequence-local position

    // load x (main + halo)
    for (int i = tid; i < PT*IND; i += 256) {
        int r = i / IND, k = i % IND;
        sx[r+3][k] = x[(size_t)(t0+r)*IND + k];
    }
    if (tid < 3*IND) {
        int r = tid / IND, k = tid % IND;
        sx[r][k] = (l0 - 3 + r >= 0) ? x[(size_t)(t0 - 3 + r)*IND + k] : 0.f;
    }
    for (int i = tid; i < DXBC*4; i += 256) scw[i] = cw[i];
    if (tid < DXBC) scb[tid] = cb[tid];
    __syncthreads();

    // halo pre-conv xBC (3 x 192)
    for (int e = tid; e < 3*DXBC; e += 256) {
        int r = e / DXBC, cc = e % DXBC;
        float acc = 0.f;
        if (l0 - 3 + r >= 0) {
            acc = g_bc[DI + cc];
            #pragma unroll 8
            for (int k = 0; k < IND; k++) acc += sx[r][k] * g_Wc[k*DPROJ + DI + cc];
        }
        sxbc[r][cc] = acc;
    }

    // main GEMM: 32 tokens x 324 cols, 4x4 register tiles
    for (int tile = tid; tile < 8*81; tile += 256) {
        int tq = tile / 81, cq = tile % 81;
        int c0 = cq * 4;
        float acc[4][4] = {};
        #pragma unroll 4
        for (int k = 0; k < IND; k++) {
            float4 w = *reinterpret_cast<const float4*>(g_Wc + k*DPROJ + c0);
            #pragma unroll
            for (int i = 0; i < 4; i++) {
                float hv = sx[3 + tq*4 + i][k];
                acc[i][0] += hv*w.x; acc[i][1] += hv*w.y;
                acc[i][2] += hv*w.z; acc[i][3] += hv*w.w;
            }
        }
        float4 bcv = *reinterpret_cast<const float4*>(g_bc + c0);
        float bb4[4] = {bcv.x, bcv.y, bcv.z, bcv.w};
        #pragma unroll
        for (int i = 0; i < 4; i++) {
            int tt = tq*4 + i;
            int tok = t0 + tt;
            #pragma unroll
            for (int j = 0; j < 4; j++) {
                int cc = c0 + j;
                float v = acc[i][j] + bb4[j];
                if (cc < DI) {
                    g_z[(size_t)tok*DI + cc] = silu_f(v);
                } else if (cc < DI + DXBC) {
                    sxbc[tt + 3][cc - DI] = v;
                } else {
                    int hd = cc - (DI + DXBC);
                    g_dt[(size_t)tok*HH + hd] = softplus_f(v + dt_bias[hd]);
                }
            }
        }
    }
    __syncthreads();

    // depthwise conv(4) + silu -> g_xbc2
    for (int e = tid; e < PT*DXBC; e += 256) {
        int t = e / DXBC, c = e % DXBC;
        float acc = scb[c];
        #pragma unroll
        for (int k = 0; k < 4; k++)
            acc += scw[c*4 + k] * sxbc[t + k][c];
        g_xbc2[(size_t)(t0+t)*DXBC + c] = silu_f(acc);
    }
}

// ---------------- K_phaseA: chunk-local scan, 2x2 tiles + float2 ----------------
__global__ void k_phaseA(const float* __restrict__ A_log,
                         const float* __restrict__ Dp) {
    int bid = blockIdx.x;
    int c  = bid % NC;
    int bh = bid / NC;
    int hd = bh % HH;
    int b  = bh / HH;
    int tid = threadIdx.x;

    __shared__ __align__(16) float sx[QQ][34], sB[QQ][34], sC[QQ][34];
    __shared__ __align__(16) float sM[QQ][34], sxwT[QQ][34];
    __shared__ float sdt[QQ], salpha[QQ], sE[QQ], sF[QQ], sw_[QQ];

    size_t lbase = (size_t)b*LL + (size_t)c*QQ;

    // vector loads: x slice, B, C (each 32x32 floats) as float2 into stride-34 rows
    {
        const float2* gsrc = reinterpret_cast<const float2*>(g_xbc2);
        for (int i = tid; i < 1536; i += 256) {
            int a = i >> 9, rem = i & 511;
            int r = rem >> 4, n2 = rem & 15;
            int offh = (a == 0) ? hd*16 : (a == 1 ? 64 : 80);
            float2 v = gsrc[(lbase + r)*96 + offh + n2];
            float* dst = (a == 0) ? &sx[0][0] : (a == 1 ? &sB[0][0] : &sC[0][0]);
            *reinterpret_cast<float2*>(dst + r*34 + 2*n2) = v;
        }
    }
    if (tid < QQ) {
        float A = -__expf(A_log[hd]);
        float v = g_dt[(lbase + tid)*HH + hd];
        sdt[tid] = v;
        float a = v * A;
        #pragma unroll
        for (int o = 1; o < 32; o <<= 1) {
            float n = __shfl_up_sync(0xffffffffu, a, o);
            if (tid >= o) a += n;
        }
        salpha[tid] = a;
        g_alpha[(size_t)bh*LL + c*QQ + tid] = a;
    }
    __syncthreads();
    if (tid < QQ) {
        float am = salpha[16];
        float al = salpha[tid];
        sE[tid]  = __expf(al - am);
        sF[tid]  = __expf(am - al) * sdt[tid];
        sw_[tid] = __expf(salpha[31] - al) * sdt[tid];
        if (tid == 0) g_cdecay[bid] = __expf(salpha[31]);
    }
    __syncthreads();

    int i = tid >> 4, j = tid & 15;

    // pass 1: M[t][s] = (C_t.B_s) * E[t]*F[s] (lower tri); tile rows {i,i+16} x {j,j+16}
    {
        float a00 = 0.f, a10 = 0.f, a11 = 0.f;
        #pragma unroll
        for (int n2 = 0; n2 < 16; n2++) {
            float2 c0 = *reinterpret_cast<float2*>(&sC[i][2*n2]);
            float2 c1 = *reinterpret_cast<float2*>(&sC[i+16][2*n2]);
            float2 b0 = *reinterpret_cast<float2*>(&sB[j][2*n2]);
            float2 b1 = *reinterpret_cast<float2*>(&sB[j+16][2*n2]);
            a00 += c0.x*b0.x + c0.y*b0.y;
            a10 += c1.x*b0.x + c1.y*b0.y;
            a11 += c1.x*b1.x + c1.y*b1.y;
        }
        sM[i][j]       = (j <= i) ? a00 * sE[i]    * sF[j]    : 0.f;
        sM[i][j+16]    = 0.f;                                  // s=j+16 > i always
        sM[i+16][j]    =            a10 * sE[i+16] * sF[j];    // s=j <= i+16 always
        sM[i+16][j+16] = (j <= i) ? a11 * sE[i+16] * sF[j+16] : 0.f;
    }
    // weighted x, transposed: xwT[p][s] = w[s]*x[s][p]
    for (int e = tid; e < QQ*32; e += 256) {
        int s = e >> 5, p = e & 31;
        sxwT[p][s] = sw_[s] * sx[s][p];
    }
    __syncthreads();

    // pass 2: Y[t][p] = D*x + sum_s M[t][s] x[s][p];  t in {i,i+16}, p in {2j,2j+1}
    {
        float2 y0 = {0.f, 0.f}, y1 = {0.f, 0.f};
        int lim0 = (i >> 1) + 1;
        #pragma unroll 4
        for (int s2 = 0; s2 < lim0; s2++) {
            float2 m0 = *reinterpret_cast<float2*>(&sM[i][2*s2]);
            float2 m1 = *reinterpret_cast<float2*>(&sM[i+16][2*s2]);
            float2 x0 = *reinterpret_cast<float2*>(&sx[2*s2][2*j]);
            float2 x1 = *reinterpret_cast<float2*>(&sx[2*s2+1][2*j]);
            y0.x += m0.x*x0.x + m0.y*x1.x;  y0.y += m0.x*x0.y + m0.y*x1.y;
            y1.x += m1.x*x0.x + m1.y*x1.x;  y1.y += m1.x*x0.y + m1.y*x1.y;
        }
        #pragma unroll 4
        for (int s2 = lim0; s2 < lim0 + 8; s2++) {
            float2 m1 = *reinterpret_cast<float2*>(&sM[i+16][2*s2]);
            float2 x0 = *reinterpret_cast<float2*>(&sx[2*s2][2*j]);
            float2 x1 = *reinterpret_cast<float2*>(&sx[2*s2+1][2*j]);
            y1.x += m1.x*x0.x + m1.y*x1.x;  y1.y += m1.x*x0.y + m1.y*x1.y;
        }
        float Dh = Dp[hd];
        float2 xt0 = *reinterpret_cast<float2*>(&sx[i][2*j]);
        float2 xt1 = *reinterpret_cast<float2*>(&sx[i+16][2*j]);
        y0.x += Dh*xt0.x; y0.y += Dh*xt0.y;
        y1.x += Dh*xt1.x; y1.y += Dh*xt1.y;
        *reinterpret_cast<float2*>(&g_y[(lbase + i   )*DI + hd*PP + 2*j]) = y0;
        *reinterpret_cast<float2*>(&g_y[(lbase + i+16)*DI + hd*PP + 2*j]) = y1;
    }
    // pass 3: S[p][n] = sum_s xw[s][p] B[s][n];  p in {i,i+16}, n in {2j,2j+1}
    {
        float2 s0 = {0.f, 0.f}, s1 = {0.f, 0.f};
        #pragma unroll
        for (int s2 = 0; s2 < 16; s2++) {
            float2 w0 = *reinterpret_cast<float2*>(&sxwT[i][2*s2]);
            float2 w1 = *reinterpret_cast<float2*>(&sxwT[i+16][2*s2]);
            float2 b0 = *reinterpret_cast<float2*>(&sB[2*s2][2*j]);
            float2 b1 = *reinterpret_cast<float2*>(&sB[2*s2+1][2*j]);
            s0.x += w0.x*b0.x + w0.y*b1.x;  s0.y += w0.x*b0.y + w0.y*b1.y;
            s1.x += w1.x*b0.x + w1.y*b1.x;  s1.y += w1.x*b0.y + w1.y*b1.y;
        }
        *reinterpret_cast<float2*>(&g_S[(size_t)bid*1024 + i*32      + 2*j]) = s0;
        *reinterpret_cast<float2*>(&g_S[(size_t)bid*1024 + (i+16)*32 + 2*j]) = s1;
    }
}

// ---------------- K_phaseB: sequential state recurrence over chunks ----------------
__global__ void k_phaseB() {
    int idx = blockIdx.x*256 + threadIdx.x;      // 0..65535
    int pn = idx & 1023;
    int bh = idx >> 10;
    float hcur = 0.f;
    #pragma unroll 4
    for (int c = 0; c < NC; c++) {
        size_t o = ((size_t)bh*NC + c)*1024 + pn;
        g_H0[o] = hcur;
        hcur = g_cdecay[bh*NC + c]*hcur + g_S[o];
    }
}

// ---------------- K_phaseC: inter-chunk contribution, 2x2 tiles ----------------
__global__ void k_phaseC() {
    int bid = blockIdx.x;
    int c  = bid % NC;
    if (c == 0) return;                          // H0 == 0
    int bh = bid / NC;
    int hd = bh % HH;
    int b  = bh / HH;
    int tid = threadIdx.x;

    __shared__ __align__(16) float sHT[NN][34];  // H transposed: [n][p]
    __shared__ __align__(16) float sC[QQ][34];
    __shared__ float sea[QQ];

    size_t lbase = (size_t)b*LL + (size_t)c*QQ;

    for (int e = tid; e < PP*NN; e += 256) {
        float v = g_H0[(size_t)bid*1024 + e];    // [p][n]
        sHT[e & 31][e >> 5] = v;
    }
    {
        const float2* gsrc = reinterpret_cast<const float2*>(g_xbc2);
        for (int i = tid; i < 512; i += 256) {
            int r = i >> 4, n2 = i & 15;
            float2 v = gsrc[(lbase + r)*96 + 80 + n2];
            *reinterpret_cast<float2*>(&sC[r][2*n2]) = v;
        }
    }
    if (tid < QQ) sea[tid] = __expf(g_alpha[(size_t)bh*LL + c*QQ + tid]);
    __syncthreads();

    int i = tid >> 4, j = tid & 15;
    float2 a0 = {0.f, 0.f}, a1 = {0.f, 0.f};     // t in {i,i+16}, p in {2j,2j+1}
    #pragma unroll
    for (int n2 = 0; n2 < 16; n2++) {
        float2 c0 = *reinterpret_cast<float2*>(&sC[i][2*n2]);
        float2 c1 = *reinterpret_cast<float2*>(&sC[i+16][2*n2]);
        float2 h0 = *reinterpret_cast<float2*>(&sHT[2*n2][2*j]);
        float2 h1 = *reinterpret_cast<float2*>(&sHT[2*n2+1][2*j]);
        a0.x += c0.x*h0.x + c0.y*h1.x;  a0.y += c0.x*h0.y + c0.y*h1.y;
        a1.x += c1.x*h0.x + c1.y*h1.x;  a1.y += c1.x*h0.y + c1.y*h1.y;
    }
    float e0 = sea[i], e1 = sea[i+16];
    {
        float2* yp = reinterpret_cast<float2*>(&g_y[(lbase + i)*DI + hd*PP + 2*j]);
        float2 y = *yp; y.x += e0*a0.x; y.y += e0*a0.y; *yp = y;
    }
    {
        float2* yp = reinterpret_cast<float2*>(&g_y[(lbase + i+16)*DI + hd*PP + 2*j]);
        float2 y = *yp; y.x += e1*a1.x; y.y += e1*a1.y; *yp = y;
    }
}

// ---------------- K_gate_pool: y*silu(z), RMSNorm, pool over L ----------------
__global__ void k_gate_pool(const float* __restrict__ nw) {
    __shared__ float sv[64][132];
    __shared__ float srms[64];
    int b   = blockIdx.x >> 5;
    int lt0 = (blockIdx.x & 31) << 6;
    int tid  = threadIdx.x;
    int w    = tid >> 5;
    int lane = tid & 31;

    #pragma unroll
    for (int tt = 0; tt < 8; tt++) {
        int t = w*8 + tt;
        size_t o = ((size_t)b*LL + lt0 + t)*DI + lane*4;
        float4 yv = *reinterpret_cast<const float4*>(&g_y[o]);
        float4 zv = *reinterpret_cast<const float4*>(&g_z[o]);
        float4 v = {yv.x*zv.x, yv.y*zv.y, yv.z*zv.z, yv.w*zv.w};
        *reinterpret_cast<float4*>(&sv[t][lane*4]) = v;
        float ss = v.x*v.x + v.y*v.y + v.z*v.z + v.w*v.w;
        #pragma unroll
        for (int o2 = 16; o2 > 0; o2 >>= 1)
            ss += __shfl_xor_sync(0xffffffffu, ss, o2);
        if (lane == 0) srms[t] = rsqrtf(ss*(1.f/DI) + 1e-5f);
    }
    __syncthreads();

    int p  = tid & 127;
    int g2 = tid >> 7;
    float acc = 0.f;
    #pragma unroll 8
    for (int t = g2*32; t < g2*32 + 32; t++) acc += sv[t][p]*srms[t];
    atomicAdd(&g_pool[b*DI + p], acc*nw[p]);
}

// ---------------- K_final: (pool/L) @ W_out @ W_cls + b_cls ----------------
__global__ void k_final(const float* __restrict__ Wout,
                        const float* __restrict__ Wcls,
                        const float* __restrict__ bcls,
                        float* __restrict__ out) {
    __shared__ float sp[BB][DI];
    __shared__ float st[BB][DM+1];
    int tid = threadIdx.x;
    for (int i = tid; i < BB*DI; i += 256)
        sp[i>>7][i&127] = g_pool[i] * (1.f/LL);
    __syncthreads();
    for (int i = tid; i < BB*DM; i += 256) {
        int bb = i >> 6, j = i & 63;
        float acc = 0.f;
        #pragma unroll 8
        for (int p = 0; p < DI; p++) acc += sp[bb][p]*Wout[p*DM + j];
        st[bb][j] = acc;
    }
    __syncthreads();
    if (tid < BB*6) {
        int bb = tid / 6, o = tid % 6;
        float acc = bcls[o];
        #pragma unroll 8
        for (int j = 0; j < DM; j++) acc += st[bb][j]*Wcls[j*6 + o];
        out[bb*6 + o] = acc;
    }
}

// ---------------- launcher ----------------
extern "C" void kernel_launch(void* const* d_in, const int* in_sizes, int n_in,
                              void* d_out, int out_size) {
    const float* x       = (const float*)d_in[0];
    const float* W_lin   = (const float*)d_in[1];
    const float* b_lin   = (const float*)d_in[2];
    const float* W_in    = (const float*)d_in[3];
    const float* conv_w  = (const float*)d_in[4];
    const float* conv_b  = (const float*)d_in[5];
    const float* dt_bias = (const float*)d_in[6];
    const float* A_log   = (const float*)d_in[7];
    const float* Dp      = (const float*)d_in[8];
    const float* norm_w  = (const float*)d_in[9];
    const float* W_out   = (const float*)d_in[10];
    const float* W_cls   = (const float*)d_in[11];
    const float* b_cls   = (const float*)d_in[12];
    float* out = (float*)d_out;

    k_pre<<<74, 256>>>(W_lin, b_lin, W_in);
    k_proj<<<TT/PT, 256>>>(x, conv_w, conv_b, dt_bias);
    k_phaseA<<<BB*HH*NC, 256>>>(A_log, Dp);
    k_phaseB<<<(BB*HH*PP*NN)/256, 256>>>();
    k_phaseC<<<BB*HH*NC, 256>>>();
    k_gate_pool<<<BB*(LL/64), 256>>>(norm_w);
    k_final<<<1, 256>>>(W_out, W_cls, b_cls, out);
}

// round 9
// speedup vs baseline: 1.3297x; 1.0013x over previous
#include <cuda_runtime.h>
#include <cuda_bf16.h>

// ---------------- problem constants ----------------
#define BB 16
#define LL 2048
#define TT (BB*LL)          // 32768 tokens
#define IND 57
#define DM 64
#define DI 128              // d_inner
#define HH 4                // heads
#define PP 32               // headdim
#define NN 32               // d_state
#define DXBC 192
#define DPROJ 324
#define QQ 32               // chunk length
#define NC (LL/QQ)          // 64 chunks per sequence
#define PT 32               // tokens per proj block

// ---------------- scratch (device globals; no runtime alloc) ----------------
__device__ float g_Wc[IND*DPROJ];     // fused W_lin@W_in
__device__ float g_bc[DPROJ];         // fused bias
__device__ float g_z[TT*DI];          // silu(z)
__device__ float g_xbc2[TT*DXBC];     // post conv+silu
__device__ float g_dt[TT*HH];         // softplus(dt + bias)
__device__ float g_alpha[BB*HH*LL];   // within-chunk inclusive cumsum of dt*A
__device__ float g_y[TT*DI];          // scan output
__device__ float g_S[BB*HH*NC*PP*NN]; // chunk-local states
__device__ float g_H0[BB*HH*NC*PP*NN];// state entering each chunk
__device__ float g_cdecay[BB*HH*NC];
__device__ float g_pool[BB*DI];

__device__ __forceinline__ float silu_f(float v) {
    return v / (1.f + __expf(-v));
}
__device__ __forceinline__ float softplus_f(float v) {
    return (v > 15.f) ? v : log1pf(__expf(v));
}

// ---------------- K_pre: fused weight/bias + zero pool ----------------
// blocks 0..72: Wc/bc elements; block 73: zero g_pool
__global__ void k_pre(const float* __restrict__ Wl,
                      const float* __restrict__ bl,
                      const float* __restrict__ Win) {
    if (blockIdx.x == 73) {
        for (int i = threadIdx.x; i < BB*DI; i += 256) g_pool[i] = 0.f;
        return;
    }
    int idx = blockIdx.x * 256 + threadIdx.x;
    if (idx < IND*DPROJ) {
        int k = idx / DPROJ, c = idx % DPROJ;
        float acc = 0.f;
        #pragma unroll 8
        for (int m = 0; m < DM; m++) acc += Wl[k*DM + m] * Win[m*DPROJ + c];
        g_Wc[idx] = acc;
    } else if (idx < IND*DPROJ + DPROJ) {
        int c = idx - IND*DPROJ;
        float acc = 0.f;
        #pragma unroll 8
        for (int m = 0; m < DM; m++) acc += bl[m] * Win[m*DPROJ + c];
        g_bc[c] = acc;
    }
}

// ---------------- K_proj: x -> (z, xBC[conv+silu], dt) fused ----------------
// block = 32 tokens + 3-token halo recompute, 256 threads
__global__ void k_proj(const float* __restrict__ x,
                       const float* __restrict__ cw,
                       const float* __restrict__ cb,
                       const float* __restrict__ dt_bias) {
    __shared__ float sx[PT+3][IND];        // rows 0..2 halo, 3..34 main
    __shared__ float sxbc[PT+3][196];      // pre-conv xBC
    __shared__ float scw[DXBC*4];
    __shared__ float scb[DXBC];
    int tid = threadIdx.x;
    int t0  = blockIdx.x * PT;
    int l0  = t0 & (LL-1);                 // sequence-local position

    // load x (main + halo)
    for (int i = tid; i < PT*IND; i += 256) {
        int r = i / IND, k = i % IND;
        sx[r+3][k] = x[(size_t)(t0+r)*IND + k];
    }
    if (tid < 3*IND) {
        int r = tid / IND, k = tid % IND;
        sx[r][k] = (l0 - 3 + r >= 0) ? x[(size_t)(t0 - 3 + r)*IND + k] : 0.f;
    }
    for (int i = tid; i < DXBC*4; i += 256) scw[i] = cw[i];
    if (tid < DXBC) scb[tid] = cb[tid];
    __syncthreads();

    // halo pre-conv xBC (3 x 192)
    for (int e = tid; e < 3*DXBC; e += 256) {
        int r = e / DXBC, cc = e % DXBC;
        float acc = 0.f;
        if (l0 - 3 + r >= 0) {
            acc = g_bc[DI + cc];
            #pragma unroll 8
            for (int k = 0; k < IND; k++) acc += sx[r][k] * g_Wc[k*DPROJ + DI + cc];
        }
        sxbc[r][cc] = acc;
    }

    // main GEMM: 32 tokens x 324 cols, 4x4 register tiles
    for (int tile = tid; tile < 8*81; tile += 256) {
        int tq = tile / 81, cq = tile % 81;
        int c0 = cq * 4;
        float acc[4][4] = {};
        #pragma unroll 4
        for (int k = 0; k < IND; k++) {
            float4 w = *reinterpret_cast<const float4*>(g_Wc + k*DPROJ + c0);
            #pragma unroll
            for (int i = 0; i < 4; i++) {
                float hv = sx[3 + tq*4 + i][k];
                acc[i][0] += hv*w.x; acc[i][1] += hv*w.y;
                acc[i][2] += hv*w.z; acc[i][3] += hv*w.w;
            }
        }
        float4 bcv = *reinterpret_cast<const float4*>(g_bc + c0);
        float bb4[4] = {bcv.x, bcv.y, bcv.z, bcv.w};
        #pragma unroll
        for (int i = 0; i < 4; i++) {
            int tt = tq*4 + i;
            int tok = t0 + tt;
            #pragma unroll
            for (int j = 0; j < 4; j++) {
                int cc = c0 + j;
                float v = acc[i][j] + bb4[j];
                if (cc < DI) {
                    g_z[(size_t)tok*DI + cc] = silu_f(v);
                } else if (cc < DI + DXBC) {
                    sxbc[tt + 3][cc - DI] = v;
                } else {
                    int hd = cc - (DI + DXBC);
                    g_dt[(size_t)tok*HH + hd] = softplus_f(v + dt_bias[hd]);
                }
            }
        }
    }
    __syncthreads();

    // depthwise conv(4) + silu -> g_xbc2
    for (int e = tid; e < PT*DXBC; e += 256) {
        int t = e / DXBC, c = e % DXBC;
        float acc = scb[c];
        #pragma unroll
        for (int k = 0; k < 4; k++)
            acc += scw[c*4 + k] * sxbc[t + k][c];
        g_xbc2[(size_t)(t0+t)*DXBC + c] = silu_f(acc);
    }
}

// ---------------- K_phaseA: chunk-local scan, 2x2 tiles + float2 ----------------
__global__ void k_phaseA(const float* __restrict__ A_log,
                         const float* __restrict__ Dp) {
    int bid = blockIdx.x;
    int c  = bid % NC;
    int bh = bid / NC;
    int hd = bh % HH;
    int b  = bh / HH;
    int tid = threadIdx.x;

    __shared__ __align__(16) float sx[QQ][34], sB[QQ][34], sC[QQ][34];
    __shared__ __align__(16) float sM[QQ][34], sxwT[QQ][34];
    __shared__ float sdt[QQ], salpha[QQ], sE[QQ], sF[QQ], sw_[QQ];

    size_t lbase = (size_t)b*LL + (size_t)c*QQ;

    // vector loads: x slice, B, C (each 32x32 floats) as float2 into stride-34 rows
    {
        const float2* gsrc = reinterpret_cast<const float2*>(g_xbc2);
        for (int i = tid; i < 1536; i += 256) {
            int a = i >> 9, rem = i & 511;
            int r = rem >> 4, n2 = rem & 15;
            int offh = (a == 0) ? hd*16 : (a == 1 ? 64 : 80);
            float2 v = gsrc[(lbase + r)*96 + offh + n2];
            float* dst = (a == 0) ? &sx[0][0] : (a == 1 ? &sB[0][0] : &sC[0][0]);
            *reinterpret_cast<float2*>(dst + r*34 + 2*n2) = v;
        }
    }
    if (tid < QQ) {
        float A = -__expf(A_log[hd]);
        float v = g_dt[(lbase + tid)*HH + hd];
        sdt[tid] = v;
        float a = v * A;
        #pragma unroll
        for (int o = 1; o < 32; o <<= 1) {
            float n = __shfl_up_sync(0xffffffffu, a, o);
            if (tid >= o) a += n;
        }
        salpha[tid] = a;
        g_alpha[(size_t)bh*LL + c*QQ + tid] = a;
    }
    __syncthreads();
    if (tid < QQ) {
        float am = salpha[16];
        float al = salpha[tid];
        sE[tid]  = __expf(al - am);
        sF[tid]  = __expf(am - al) * sdt[tid];
        sw_[tid] = __expf(salpha[31] - al) * sdt[tid];
        if (tid == 0) g_cdecay[bid] = __expf(salpha[31]);
    }
    __syncthreads();

    int i = tid >> 4, j = tid & 15;

    // pass 1: M[t][s] = (C_t.B_s) * E[t]*F[s] (lower tri); tile rows {i,i+16} x {j,j+16}
    {
        float a00 = 0.f, a10 = 0.f, a11 = 0.f;
        #pragma unroll
        for (int n2 = 0; n2 < 16; n2++) {
            float2 c0 = *reinterpret_cast<float2*>(&sC[i][2*n2]);
            float2 c1 = *reinterpret_cast<float2*>(&sC[i+16][2*n2]);
            float2 b0 = *reinterpret_cast<float2*>(&sB[j][2*n2]);
            float2 b1 = *reinterpret_cast<float2*>(&sB[j+16][2*n2]);
            a00 += c0.x*b0.x + c0.y*b0.y;
            a10 += c1.x*b0.x + c1.y*b0.y;
            a11 += c1.x*b1.x + c1.y*b1.y;
        }
        sM[i][j]       = (j <= i) ? a00 * sE[i]    * sF[j]    : 0.f;
        sM[i][j+16]    = 0.f;                                  // s=j+16 > i always
        sM[i+16][j]    =            a10 * sE[i+16] * sF[j];    // s=j <= i+16 always
        sM[i+16][j+16] = (j <= i) ? a11 * sE[i+16] * sF[j+16] : 0.f;
    }
    // weighted x, transposed: xwT[p][s] = w[s]*x[s][p]
    for (int e = tid; e < QQ*32; e += 256) {
        int s = e >> 5, p = e & 31;
        sxwT[p][s] = sw_[s] * sx[s][p];
    }
    __syncthreads();

    // pass 2: Y[t][p] = D*x + sum_s M[t][s] x[s][p];  t in {i,i+16}, p in {2j,2j+1}
    {
        float2 y0 = {0.f, 0.f}, y1 = {0.f, 0.f};
        int lim0 = (i >> 1) + 1;
        #pragma unroll 4
        for (int s2 = 0; s2 < lim0; s2++) {
            float2 m0 = *reinterpret_cast<float2*>(&sM[i][2*s2]);
            float2 m1 = *reinterpret_cast<float2*>(&sM[i+16][2*s2]);
            float2 x0 = *reinterpret_cast<float2*>(&sx[2*s2][2*j]);
            float2 x1 = *reinterpret_cast<float2*>(&sx[2*s2+1][2*j]);
            y0.x += m0.x*x0.x + m0.y*x1.x;  y0.y += m0.x*x0.y + m0.y*x1.y;
            y1.x += m1.x*x0.x + m1.y*x1.x;  y1.y += m1.x*x0.y + m1.y*x1.y;
        }
        #pragma unroll 4
        for (int s2 = lim0; s2 < lim0 + 8; s2++) {
            float2 m1 = *reinterpret_cast<float2*>(&sM[i+16][2*s2]);
            float2 x0 = *reinterpret_cast<float2*>(&sx[2*s2][2*j]);
            float2 x1 = *reinterpret_cast<float2*>(&sx[2*s2+1][2*j]);
            y1.x += m1.x*x0.x + m1.y*x1.x;  y1.y += m1.x*x0.y + m1.y*x1.y;
        }
        float Dh = Dp[hd];
        float2 xt0 = *reinterpret_cast<float2*>(&sx[i][2*j]);
        float2 xt1 = *reinterpret_cast<float2*>(&sx[i+16][2*j]);
        y0.x += Dh*xt0.x; y0.y += Dh*xt0.y;
        y1.x += Dh*xt1.x; y1.y += Dh*xt1.y;
        *reinterpret_cast<float2*>(&g_y[(lbase + i   )*DI + hd*PP + 2*j]) = y0;
        *reinterpret_cast<float2*>(&g_y[(lbase + i+16)*DI + hd*PP + 2*j]) = y1;
    }
    // pass 3: S[p][n] = sum_s xw[s][p] B[s][n];  p in {i,i+16}, n in {2j,2j+1}
    {
        float2 s0 = {0.f, 0.f}, s1 = {0.f, 0.f};
        #pragma unroll
        for (int s2 = 0; s2 < 16; s2++) {
            float2 w0 = *reinterpret_cast<float2*>(&sxwT[i][2*s2]);
            float2 w1 = *reinterpret_cast<float2*>(&sxwT[i+16][2*s2]);
            float2 b0 = *reinterpret_cast<float2*>(&sB[2*s2][2*j]);
            float2 b1 = *reinterpret_cast<float2*>(&sB[2*s2+1][2*j]);
            s0.x += w0.x*b0.x + w0.y*b1.x;  s0.y += w0.x*b0.y + w0.y*b1.y;
            s1.x += w1.x*b0.x + w1.y*b1.x;  s1.y += w1.x*b0.y + w1.y*b1.y;
        }
        *reinterpret_cast<float2*>(&g_S[(size_t)bid*1024 + i*32      + 2*j]) = s0;
        *reinterpret_cast<float2*>(&g_S[(size_t)bid*1024 + (i+16)*32 + 2*j]) = s1;
    }
}

// ---------------- K_phaseB: sequential state recurrence over chunks ----------------
__global__ void k_phaseB() {
    int idx = blockIdx.x*256 + threadIdx.x;      // 0..65535
    int pn = idx & 1023;
    int bh = idx >> 10;
    float hcur = 0.f;
    #pragma unroll 4
    for (int c = 0; c < NC; c++) {
        size_t o = ((size_t)bh*NC + c)*1024 + pn;
        g_H0[o] = hcur;
        hcur = g_cdecay[bh*NC + c]*hcur + g_S[o];
    }
}

// ---------------- K_phaseC: inter-chunk contribution, 2x2 tiles ----------------
__global__ void k_phaseC() {
    int bid = blockIdx.x;
    int c  = bid % NC;
    if (c == 0) return;                          // H0 == 0
    int bh = bid / NC;
    int hd = bh % HH;
    int b  = bh / HH;
    int tid = threadIdx.x;

    __shared__ __align__(16) float sHT[NN][34];  // H transposed: [n][p]
    __shared__ __align__(16) float sC[QQ][34];
    __shared__ float sea[QQ];

    size_t lbase = (size_t)b*LL + (size_t)c*QQ;

    for (int e = tid; e < PP*NN; e += 256) {
        float v = g_H0[(size_t)bid*1024 + e];    // [p][n]
        sHT[e & 31][e >> 5] = v;
    }
    {
        const float2* gsrc = reinterpret_cast<const float2*>(g_xbc2);
        for (int i = tid; i < 512; i += 256) {
            int r = i >> 4, n2 = i & 15;
            float2 v = gsrc[(lbase + r)*96 + 80 + n2];
            *reinterpret_cast<float2*>(&sC[r][2*n2]) = v;
        }
    }
    if (tid < QQ) sea[tid] = __expf(g_alpha[(size_t)bh*LL + c*QQ + tid]);
    __syncthreads();

    int i = tid >> 4, j = tid & 15;
    float2 a0 = {0.f, 0.f}, a1 = {0.f, 0.f};     // t in {i,i+16}, p in {2j,2j+1}
    #pragma unroll
    for (int n2 = 0; n2 < 16; n2++) {
        float2 c0 = *reinterpret_cast<float2*>(&sC[i][2*n2]);
        float2 c1 = *reinterpret_cast<float2*>(&sC[i+16][2*n2]);
        float2 h0 = *reinterpret_cast<float2*>(&sHT[2*n2][2*j]);
        float2 h1 = *reinterpret_cast<float2*>(&sHT[2*n2+1][2*j]);
        a0.x += c0.x*h0.x + c0.y*h1.x;  a0.y += c0.x*h0.y + c0.y*h1.y;
        a1.x += c1.x*h0.x + c1.y*h1.x;  a1.y += c1.x*h0.y + c1.y*h1.y;
    }
    float e0 = sea[i], e1 = sea[i+16];
    {
        float2* yp = reinterpret_cast<float2*>(&g_y[(lbase + i)*DI + hd*PP + 2*j]);
        float2 y = *yp; y.x += e0*a0.x; y.y += e0*a0.y; *yp = y;
    }
    {
        float2* yp = reinterpret_cast<float2*>(&g_y[(lbase + i+16)*DI + hd*PP + 2*j]);
        float2 y = *yp; y.x += e1*a1.x; y.y += e1*a1.y; *yp = y;
    }
}

// ---------------- K_gate_pool: y*silu(z), RMSNorm, pool over L ----------------
__global__ void k_gate_pool(const float* __restrict__ nw) {
    __shared__ float sv[64][132];
    __shared__ float srms[64];
    int b   = blockIdx.x >> 5;
    int lt0 = (blockIdx.x & 31) << 6;
    int tid  = threadIdx.x;
    int w    = tid >> 5;
    int lane = tid & 31;

    #pragma unroll
    for (int tt = 0; tt < 8; tt++) {
        int t = w*8 + tt;
        size_t o = ((size_t)b*LL + lt0 + t)*DI + lane*4;
        float4 yv = *reinterpret_cast<const float4*>(&g_y[o]);
        float4 zv = *reinterpret_cast<const float4*>(&g_z[o]);
        float4 v = {yv.x*zv.x, yv.y*zv.y, yv.z*zv.z, yv.w*zv.w};
        *reinterpret_cast<float4*>(&sv[t][lane*4]) = v;
        float ss = v.x*v.x + v.y*v.y + v.z*v.z + v.w*v.w;
        #pragma unroll
        for (int o2 = 16; o2 > 0; o2 >>= 1)
            ss += __shfl_xor_sync(0xffffffffu, ss, o2);
        if (lane == 0) srms[t] = rsqrtf(ss*(1.f/DI) + 1e-5f);
    }
    __syncthreads();

    int p  = tid & 127;
    int g2 = tid >> 7;
    float acc = 0.f;
    #pragma unroll 8
    for (int t = g2*32; t < g2*32 + 32; t++) acc += sv[t][p]*srms[t];
    atomicAdd(&g_pool[b*DI + p], acc*nw[p]);
}

// ---------------- K_final: (pool/L) @ W_out @ W_cls + b_cls ----------------
__global__ void k_final(const float* __restrict__ Wout,
                        const float* __restrict__ Wcls,
                        const float* __restrict__ bcls,
                        float* __restrict__ out) {
    __shared__ float sp[BB][DI];
    __shared__ float st[BB][DM+1];
    int tid = threadIdx.x;
    for (int i = tid; i < BB*DI; i += 256)
        sp[i>>7][i&127] = g_pool[i] * (1.f/LL);
    __syncthreads();
    for (int i = tid; i < BB*DM; i += 256) {
        int bb = i >> 6, j = i & 63;
        float acc = 0.f;
        #pragma unroll 8
        for (int p = 0; p < DI; p++) acc += sp[bb][p]*Wout[p*DM + j];
        st[bb][j] = acc;
    }
    __syncthreads();
    if (tid < BB*6) {
        int bb = tid / 6, o = tid % 6;
        float acc = bcls[o];
        #pragma unroll 8
        for (int j = 0; j < DM; j++) acc += st[bb][j]*Wcls[j*6 + o];
        out[bb*6 + o] = acc;
    }
}

// ---------------- launcher ----------------
extern "C" void kernel_launch(void* const* d_in, const int* in_sizes, int n_in,
                              void* d_out, int out_size) {
    const float* x       = (const float*)d_in[0];
    const float* W_lin   = (const float*)d_in[1];
    const float* b_lin   = (const float*)d_in[2];
    const float* W_in    = (const float*)d_in[3];
    const float* conv_w  = (const float*)d_in[4];
    const float* conv_b  = (const float*)d_in[5];
    const float* dt_bias = (const float*)d_in[6];
    const float* A_log   = (const float*)d_in[7];
    const float* Dp      = (const float*)d_in[8];
    const float* norm_w  = (const float*)d_in[9];
    const float* W_out   = (const float*)d_in[10];
    const float* W_cls   = (const float*)d_in[11];
    const float* b_cls   = (const float*)d_in[12];
    float* out = (float*)d_out;

    k_pre<<<74, 256>>>(W_lin, b_lin, W_in);
    k_proj<<<TT/PT, 256>>>(x, conv_w, conv_b, dt_bias);
    k_phaseA<<<BB*HH*NC, 256>>>(A_log, Dp);
    k_phaseB<<<(BB*HH*PP*NN)/256, 256>>>();
    k_phaseC<<<BB*HH*NC, 256>>>();
    k_gate_pool<<<BB*(LL/64), 256>>>(norm_w);
    k_final<<<1, 256>>>(W_out, W_cls, b_cls, out);
}

// round 10
// speedup vs baseline: 1.4096x; 1.0600x over previous
#include <cuda_runtime.h>
#include <cuda_bf16.h>

// ---------------- problem constants ----------------
#define BB 16
#define LL 2048
#define TT (BB*LL)          // 32768 tokens
#define IND 57
#define DM 64
#define DI 128              // d_inner
#define HH 4                // heads
#define PP 32               // headdim
#define NN 32               // d_state
#define DXBC 192
#define DPROJ 324
#define QQ 32               // chunk length
#define NC (LL/QQ)          // 64 chunks per sequence
#define PT 32               // tokens per proj block
#define SEG 8               // chunks per scan segment
#define NSEG (NC/SEG)       // 8 segments

// ---------------- scratch (device globals; no runtime alloc) ----------------
__device__ float g_Wc[IND*DPROJ];     // fused W_lin@W_in
__device__ float g_bc[DPROJ];         // fused bias
__device__ float g_z[TT*DI];          // silu(z)
__device__ float g_xbc2[TT*DXBC];     // post conv+silu
__device__ float g_dt[TT*HH];         // softplus(dt + bias)
__device__ float g_alpha[BB*HH*LL];   // within-chunk inclusive cumsum of dt*A
__device__ float g_y[TT*DI];          // scan output
__device__ float g_S[BB*HH*NC*PP*NN]; // chunk-local states
__device__ float g_H0[BB*HH*NC*PP*NN];// segment-LOCAL state entering each chunk
__device__ float g_Sseg[BB*HH*NSEG*PP*NN]; // segment-end states
__device__ float g_carry[BB*HH*NSEG*PP*NN];// state entering each segment
__device__ float g_cdecay[BB*HH*NC];
__device__ float g_pool[BB*DI];

__device__ __forceinline__ float silu_f(float v) {
    return v / (1.f + __expf(-v));
}
__device__ __forceinline__ float softplus_f(float v) {
    return (v > 15.f) ? v : log1pf(__expf(v));
}

// ---------------- packed fp32x2 helpers (Blackwell FFMA2) ----------------
__device__ __forceinline__ float2 ffma2(float2 a, float2 b, float2 c) {
    unsigned long long ra = reinterpret_cast<unsigned long long&>(a);
    unsigned long long rb = reinterpret_cast<unsigned long long&>(b);
    unsigned long long rc = reinterpret_cast<unsigned long long&>(c);
    unsigned long long rd;
    asm("fma.rn.f32x2 %0, %1, %2, %3;" : "=l"(rd) : "l"(ra), "l"(rb), "l"(rc));
    return reinterpret_cast<float2&>(rd);
}
__device__ __forceinline__ float2 dup2(float v) {
    unsigned long long rd;
    asm("mov.b64 %0, {%1, %1};" : "=l"(rd) : "r"(__float_as_uint(v)));
    return reinterpret_cast<float2&>(rd);
}

// ---------------- K_pre: fused weight/bias + zero pool ----------------
__global__ void k_pre(const float* __restrict__ Wl,
                      const float* __restrict__ bl,
                      const float* __restrict__ Win) {
    if (blockIdx.x == 73) {
        for (int i = threadIdx.x; i < BB*DI; i += 256) g_pool[i] = 0.f;
        return;
    }
    int idx = blockIdx.x * 256 + threadIdx.x;
    if (idx < IND*DPROJ) {
        int k = idx / DPROJ, c = idx % DPROJ;
        float acc = 0.f;
        #pragma unroll 8
        for (int m = 0; m < DM; m++) acc += Wl[k*DM + m] * Win[m*DPROJ + c];
        g_Wc[idx] = acc;
    } else if (idx < IND*DPROJ + DPROJ) {
        int c = idx - IND*DPROJ;
        float acc = 0.f;
        #pragma unroll 8
        for (int m = 0; m < DM; m++) acc += bl[m] * Win[m*DPROJ + c];
        g_bc[c] = acc;
    }
}

// ---------------- K_proj: x -> (z, xBC[conv+silu], dt), FFMA2 tiles ----------------
__global__ void k_proj(const float* __restrict__ x,
                       const float* __restrict__ cw,
                       const float* __restrict__ cb,
                       const float* __restrict__ dt_bias) {
    __shared__ float sx[PT+3][IND];        // rows 0..2 halo, 3..34 main
    __shared__ float sxbc[PT+3][196];      // pre-conv xBC
    __shared__ float scw[DXBC*4];
    __shared__ float scb[DXBC];
    int tid = threadIdx.x;
    int t0  = blockIdx.x * PT;
    int l0  = t0 & (LL-1);

    for (int i = tid; i < PT*IND; i += 256) {
        int r = i / IND, k = i % IND;
        sx[r+3][k] = x[(size_t)(t0+r)*IND + k];
    }
    if (tid < 3*IND) {
        int r = tid / IND, k = tid % IND;
        sx[r][k] = (l0 - 3 + r >= 0) ? x[(size_t)(t0 - 3 + r)*IND + k] : 0.f;
    }
    for (int i = tid; i < DXBC*4; i += 256) scw[i] = cw[i];
    if (tid < DXBC) scb[tid] = cb[tid];
    __syncthreads();

    // halo pre-conv xBC (3 x 192)
    for (int e = tid; e < 3*DXBC; e += 256) {
        int r = e / DXBC, cc = e % DXBC;
        float acc = 0.f;
        if (l0 - 3 + r >= 0) {
            acc = g_bc[DI + cc];
            #pragma unroll 8
            for (int k = 0; k < IND; k++) acc += sx[r][k] * g_Wc[k*DPROJ + DI + cc];
        }
        sxbc[r][cc] = acc;
    }

    // main GEMM: 32 tokens x 324 cols, 4x4 tiles via packed FFMA2
    for (int tile = tid; tile < 8*81; tile += 256) {
        int tq = tile / 81, cq = tile % 81;
        int c0 = cq * 4;
        float2 a01[4] = {{0,0},{0,0},{0,0},{0,0}};
        float2 a23[4] = {{0,0},{0,0},{0,0},{0,0}};
        #pragma unroll 3
        for (int k = 0; k < IND; k++) {
            float4 w = *reinterpret_cast<const float4*>(g_Wc + k*DPROJ + c0);
            float2 w01 = {w.x, w.y}, w23 = {w.z, w.w};
            #pragma unroll
            for (int i = 0; i < 4; i++) {
                float2 hd = dup2(sx[3 + tq*4 + i][k]);
                a01[i] = ffma2(hd, w01, a01[i]);
                a23[i] = ffma2(hd, w23, a23[i]);
            }
        }
        float4 bcv = *reinterpret_cast<const float4*>(g_bc + c0);
        #pragma unroll
        for (int i = 0; i < 4; i++) {
            int tt = tq*4 + i;
            int tok = t0 + tt;
            float v4[4] = {a01[i].x + bcv.x, a01[i].y + bcv.y,
                           a23[i].x + bcv.z, a23[i].y + bcv.w};
            #pragma unroll
            for (int j = 0; j < 4; j++) {
                int cc = c0 + j;
                float v = v4[j];
                if (cc < DI) {
                    g_z[(size_t)tok*DI + cc] = silu_f(v);
                } else if (cc < DI + DXBC) {
                    sxbc[tt + 3][cc - DI] = v;
                } else {
                    int hd = cc - (DI + DXBC);
                    g_dt[(size_t)tok*HH + hd] = softplus_f(v + dt_bias[hd]);
                }
            }
        }
    }
    __syncthreads();

    // depthwise conv(4) + silu -> g_xbc2
    for (int e = tid; e < PT*DXBC; e += 256) {
        int t = e / DXBC, c = e % DXBC;
        float acc = scb[c];
        #pragma unroll
        for (int k = 0; k < 4; k++)
            acc += scw[c*4 + k] * sxbc[t + k][c];
        g_xbc2[(size_t)(t0+t)*DXBC + c] = silu_f(acc);
    }
}

// ---------------- K_phaseA: chunk-local scan, FFMA2 2x2 tiles ----------------
__global__ void k_phaseA(const float* __restrict__ A_log,
                         const float* __restrict__ Dp) {
    int bid = blockIdx.x;
    int c  = bid % NC;
    int bh = bid / NC;
    int hd = bh % HH;
    int b  = bh / HH;
    int tid = threadIdx.x;

    __shared__ __align__(16) float sx[QQ][34], sB[QQ][34], sC[QQ][34];
    __shared__ __align__(16) float sM[QQ][34], sxwT[QQ][34];
    __shared__ float sdt[QQ], salpha[QQ], sE[QQ], sF[QQ], sw_[QQ];

    size_t lbase = (size_t)b*LL + (size_t)c*QQ;

    {
        const float2* gsrc = reinterpret_cast<const float2*>(g_xbc2);
        for (int i = tid; i < 1536; i += 256) {
            int a = i >> 9, rem = i & 511;
            int r = rem >> 4, n2 = rem & 15;
            int offh = (a == 0) ? hd*16 : (a == 1 ? 64 : 80);
            float2 v = gsrc[(lbase + r)*96 + offh + n2];
            float* dst = (a == 0) ? &sx[0][0] : (a == 1 ? &sB[0][0] : &sC[0][0]);
            *reinterpret_cast<float2*>(dst + r*34 + 2*n2) = v;
        }
    }
    if (tid < QQ) {
        float A = -__expf(A_log[hd]);
        float v = g_dt[(lbase + tid)*HH + hd];
        sdt[tid] = v;
        float a = v * A;
        #pragma unroll
        for (int o = 1; o < 32; o <<= 1) {
            float n = __shfl_up_sync(0xffffffffu, a, o);
            if (tid >= o) a += n;
        }
        salpha[tid] = a;
        g_alpha[(size_t)bh*LL + c*QQ + tid] = a;
    }
    __syncthreads();
    if (tid < QQ) {
        float am = salpha[16];
        float al = salpha[tid];
        sE[tid]  = __expf(al - am);
        sF[tid]  = __expf(am - al) * sdt[tid];
        sw_[tid] = __expf(salpha[31] - al) * sdt[tid];
        if (tid == 0) g_cdecay[bid] = __expf(salpha[31]);
    }
    __syncthreads();

    int i = tid >> 4, j = tid & 15;

    // pass 1: packed dot products (no dups needed)
    {
        float2 p00 = {0,0}, p10 = {0,0}, p11 = {0,0};
        #pragma unroll
        for (int n2 = 0; n2 < 16; n2++) {
            float2 c0 = *reinterpret_cast<float2*>(&sC[i][2*n2]);
            float2 c1 = *reinterpret_cast<float2*>(&sC[i+16][2*n2]);
            float2 b0 = *reinterpret_cast<float2*>(&sB[j][2*n2]);
            float2 b1 = *reinterpret_cast<float2*>(&sB[j+16][2*n2]);
            p00 = ffma2(c0, b0, p00);
            p10 = ffma2(c1, b0, p10);
            p11 = ffma2(c1, b1, p11);
        }
        float a00 = p00.x + p00.y, a10 = p10.x + p10.y, a11 = p11.x + p11.y;
        sM[i][j]       = (j <= i) ? a00 * sE[i]    * sF[j]    : 0.f;
        sM[i][j+16]    = 0.f;
        sM[i+16][j]    =            a10 * sE[i+16] * sF[j];
        sM[i+16][j+16] = (j <= i) ? a11 * sE[i+16] * sF[j+16] : 0.f;
    }
    for (int e = tid; e < QQ*32; e += 256) {
        int s = e >> 5, p = e & 31;
        sxwT[p][s] = sw_[s] * sx[s][p];
    }
    __syncthreads();

    // pass 2: Y[t][p], t in {i,i+16}, p in {2j,2j+1}
    {
        float2 y0 = {0,0}, y1 = {0,0};
        int lim0 = (i >> 1) + 1;
        #pragma unroll 4
        for (int s2 = 0; s2 < lim0; s2++) {
            float2 m0 = *reinterpret_cast<float2*>(&sM[i][2*s2]);
            float2 m1 = *reinterpret_cast<float2*>(&sM[i+16][2*s2]);
            float2 x0 = *reinterpret_cast<float2*>(&sx[2*s2][2*j]);
            float2 x1 = *reinterpret_cast<float2*>(&sx[2*s2+1][2*j]);
            y0 = ffma2(dup2(m0.x), x0, y0);  y0 = ffma2(dup2(m0.y), x1, y0);
            y1 = ffma2(dup2(m1.x), x0, y1);  y1 = ffma2(dup2(m1.y), x1, y1);
        }
        #pragma unroll 4
        for (int s2 = lim0; s2 < lim0 + 8; s2++) {
            float2 m1 = *reinterpret_cast<float2*>(&sM[i+16][2*s2]);
            float2 x0 = *reinterpret_cast<float2*>(&sx[2*s2][2*j]);
            float2 x1 = *reinterpret_cast<float2*>(&sx[2*s2+1][2*j]);
            y1 = ffma2(dup2(m1.x), x0, y1);  y1 = ffma2(dup2(m1.y), x1, y1);
        }
        float2 Dh = dup2(Dp[hd]);
        float2 xt0 = *reinterpret_cast<float2*>(&sx[i][2*j]);
        float2 xt1 = *reinterpret_cast<float2*>(&sx[i+16][2*j]);
        y0 = ffma2(Dh, xt0, y0);
        y1 = ffma2(Dh, xt1, y1);
        *reinterpret_cast<float2*>(&g_y[(lbase + i   )*DI + hd*PP + 2*j]) = y0;
        *reinterpret_cast<float2*>(&g_y[(lbase + i+16)*DI + hd*PP + 2*j]) = y1;
    }
    // pass 3: S[p][n]
    {
        float2 s0 = {0,0}, s1 = {0,0};
        #pragma unroll
        for (int s2 = 0; s2 < 16; s2++) {
            float2 w0 = *reinterpret_cast<float2*>(&sxwT[i][2*s2]);
            float2 w1 = *reinterpret_cast<float2*>(&sxwT[i+16][2*s2]);
            float2 b0 = *reinterpret_cast<float2*>(&sB[2*s2][2*j]);
            float2 b1 = *reinterpret_cast<float2*>(&sB[2*s2+1][2*j]);
            s0 = ffma2(dup2(w0.x), b0, s0);  s0 = ffma2(dup2(w0.y), b1, s0);
            s1 = ffma2(dup2(w1.x), b0, s1);  s1 = ffma2(dup2(w1.y), b1, s1);
        }
        *reinterpret_cast<float2*>(&g_S[(size_t)bid*1024 + i*32      + 2*j]) = s0;
        *reinterpret_cast<float2*>(&g_S[(size_t)bid*1024 + (i+16)*32 + 2*j]) = s1;
    }
}

// ---------------- K_B1: segment-local scan (8 chunks), 8x parallelism ----------------
__global__ void k_B1() {
    int bid = blockIdx.x;                 // ((bh*NSEG)+seg)*4 + pb
    int pb  = bid & 3;
    int sb  = bid >> 2;
    int seg = sb & (NSEG-1);
    int bh  = sb >> 3;
    int pn  = pb*256 + threadIdx.x;

    float h = 0.f;
    #pragma unroll
    for (int c8 = 0; c8 < SEG; c8++) {
        int c = seg*SEG + c8;
        size_t o = ((size_t)bh*NC + c)*1024 + pn;
        g_H0[o] = h;
        h = g_cdecay[bh*NC + c]*h + g_S[o];
    }
    g_Sseg[((size_t)bh*NSEG + seg)*1024 + pn] = h;
}

// ---------------- K_B2: scan over 8 segment aggregates ----------------
__global__ void k_B2() {
    __shared__ float sdp[NSEG];
    int bid = blockIdx.x;                 // 0..255
    int bh  = bid >> 2;
    int pn  = (bid & 3)*256 + threadIdx.x;
    if (threadIdx.x < NSEG) {
        float p = 1.f;
        #pragma unroll
        for (int j = 0; j < SEG; j++)
            p *= g_cdecay[bh*NC + threadIdx.x*SEG + j];
        sdp[threadIdx.x] = p;
    }
    __syncthreads();
    float h = 0.f;
    #pragma unroll
    for (int seg = 0; seg < NSEG; seg++) {
        size_t o = ((size_t)bh*NSEG + seg)*1024 + pn;
        g_carry[o] = h;
        h = sdp[seg]*h + g_Sseg[o];
    }
}

// ---------------- K_phaseC: inter-chunk contribution (combines carry) ----------------
__global__ void k_phaseC() {
    int bid = blockIdx.x;
    int c  = bid % NC;
    if (c == 0) return;                   // incoming state is zero
    int bh = bid / NC;
    int hd = bh % HH;
    int b  = bh / HH;
    int tid = threadIdx.x;
    int seg = c >> 3;

    __shared__ __align__(16) float sHT[NN][34];  // H transposed: [n][p]
    __shared__ __align__(16) float sC[QQ][34];
    __shared__ float sea[QQ];

    size_t lbase = (size_t)b*LL + (size_t)c*QQ;

    // within-segment prefix decay product (<=7 warp-uniform L1 loads)
    float dpre = 1.f;
    for (int jj = seg*SEG; jj < c; jj++) dpre *= g_cdecay[bh*NC + jj];

    for (int e = tid; e < PP*NN; e += 256) {
        float v = g_H0[(size_t)bid*1024 + e]
                + dpre * g_carry[((size_t)bh*NSEG + seg)*1024 + e];
        sHT[e & 31][e >> 5] = v;
    }
    {
        const float2* gsrc = reinterpret_cast<const float2*>(g_xbc2);
        for (int i = tid; i < 512; i += 256) {
            int r = i >> 4, n2 = i & 15;
            float2 v = gsrc[(lbase + r)*96 + 80 + n2];
            *reinterpret_cast<float2*>(&sC[r][2*n2]) = v;
        }
    }
    if (tid < QQ) sea[tid] = __expf(g_alpha[(size_t)bh*LL + c*QQ + tid]);
    __syncthreads();

    int i = tid >> 4, j = tid & 15;
    float2 a0 = {0,0}, a1 = {0,0};
    #pragma unroll
    for (int n2 = 0; n2 < 16; n2++) {
        float2 c0 = *reinterpret_cast<float2*>(&sC[i][2*n2]);
        float2 c1 = *reinterpret_cast<float2*>(&sC[i+16][2*n2]);
        float2 h0 = *reinterpret_cast<float2*>(&sHT[2*n2][2*j]);
        float2 h1 = *reinterpret_cast<float2*>(&sHT[2*n2+1][2*j]);
        a0 = ffma2(dup2(c0.x), h0, a0);  a0 = ffma2(dup2(c0.y), h1, a0);
        a1 = ffma2(dup2(c1.x), h0, a1);  a1 = ffma2(dup2(c1.y), h1, a1);
    }
    {
        float2* yp = reinterpret_cast<float2*>(&g_y[(lbase + i)*DI + hd*PP + 2*j]);
        *yp = ffma2(dup2(sea[i]), a0, *yp);
    }
    {
        float2* yp = reinterpret_cast<float2*>(&g_y[(lbase + i+16)*DI + hd*PP + 2*j]);
        *yp = ffma2(dup2(sea[i+16]), a1, *yp);
    }
}

// ---------------- K_gate_pool: y*silu(z), RMSNorm, pool over L ----------------
__global__ void k_gate_pool(const float* __restrict__ nw) {
    __shared__ float sv[64][132];
    __shared__ float srms[64];
    int b   = blockIdx.x >> 5;
    int lt0 = (blockIdx.x & 31) << 6;
    int tid  = threadIdx.x;
    int w    = tid >> 5;
    int lane = tid & 31;

    #pragma unroll
    for (int tt = 0; tt < 8; tt++) {
        int t = w*8 + tt;
        size_t o = ((size_t)b*LL + lt0 + t)*DI + lane*4;
        float4 yv = *reinterpret_cast<const float4*>(&g_y[o]);
        float4 zv = *reinterpret_cast<const float4*>(&g_z[o]);
        float4 v = {yv.x*zv.x, yv.y*zv.y, yv.z*zv.z, yv.w*zv.w};
        *reinterpret_cast<float4*>(&sv[t][lane*4]) = v;
        float ss = v.x*v.x + v.y*v.y + v.z*v.z + v.w*v.w;
        #pragma unroll
        for (int o2 = 16; o2 > 0; o2 >>= 1)
            ss += __shfl_xor_sync(0xffffffffu, ss, o2);
        if (lane == 0) srms[t] = rsqrtf(ss*(1.f/DI) + 1e-5f);
    }
    __syncthreads();

    int p  = tid & 127;
    int g2 = tid >> 7;
    float acc = 0.f;
    #pragma unroll 8
    for (int t = g2*32; t < g2*32 + 32; t++) acc += sv[t][p]*srms[t];
    atomicAdd(&g_pool[b*DI + p], acc*nw[p]);
}

// ---------------- K_final: (pool/L) @ W_out @ W_cls + b_cls ----------------
__global__ void k_final(const float* __restrict__ Wout,
                        const float* __restrict__ Wcls,
                        const float* __restrict__ bcls,
                        float* __restrict__ out) {
    __shared__ float sp[BB][DI];
    __shared__ float st[BB][DM+1];
    int tid = threadIdx.x;
    for (int i = tid; i < BB*DI; i += 256)
        sp[i>>7][i&127] = g_pool[i] * (1.f/LL);
    __syncthreads();
    for (int i = tid; i < BB*DM; i += 256) {
        int bb = i >> 6, j = i & 63;
        float acc = 0.f;
        #pragma unroll 8
        for (int p = 0; p < DI; p++) acc += sp[bb][p]*Wout[p*DM + j];
        st[bb][j] = acc;
    }
    __syncthreads();
    if (tid < BB*6) {
        int bb = tid / 6, o = tid % 6;
        float acc = bcls[o];
        #pragma unroll 8
        for (int j = 0; j < DM; j++) acc += st[bb][j]*Wcls[j*6 + o];
        out[bb*6 + o] = acc;
    }
}

// ---------------- launcher ----------------
extern "C" void kernel_launch(void* const* d_in, const int* in_sizes, int n_in,
                              void* d_out, int out_size) {
    const float* x       = (const float*)d_in[0];
    const float* W_lin   = (const float*)d_in[1];
    const float* b_lin   = (const float*)d_in[2];
    const float* W_in    = (const float*)d_in[3];
    const float* conv_w  = (const float*)d_in[4];
    const float* conv_b  = (const float*)d_in[5];
    const float* dt_bias = (const float*)d_in[6];
    const float* A_log   = (const float*)d_in[7];
    const float* Dp      = (const float*)d_in[8];
    const float* norm_w  = (const float*)d_in[9];
    const float* W_out   = (const float*)d_in[10];
    const float* W_cls   = (const float*)d_in[11];
    const float* b_cls   = (const float*)d_in[12];
    float* out = (float*)d_out;

    k_pre<<<74, 256>>>(W_lin, b_lin, W_in);
    k_proj<<<TT/PT, 256>>>(x, conv_w, conv_b, dt_bias);
    k_phaseA<<<BB*HH*NC, 256>>>(A_log, Dp);
    k_B1<<<BB*HH*NSEG*4, 256>>>();
    k_B2<<<256, 256>>>();
    k_phaseC<<<BB*HH*NC, 256>>>();
    k_gate_pool<<<BB*(LL/64), 256>>>(norm_w);
    k_final<<<1, 256>>>(W_out, W_cls, b_cls, out);
}